// round 1
// baseline (speedup 1.0000x reference)
#include <cuda_runtime.h>
#include <cuda_bf16.h>
#include <math.h>

// Problem constants
#define BATCH   8
#define SEQ     2048
#define NTOK    (BATCH*SEQ)      // 16384
#define FDIM    128
#define DMODEL  512
#define DINNER  1024
#define NLAYERS 4
#define VOCAB   256
#define NHEADS  (FDIM + VOCAB)   // 384

// ---------------- scratch (static device globals; no allocs) ----------------
__device__ float g_x [NTOK * DMODEL];     // residual stream
__device__ float g_n [NTOK * DMODEL];     // layernorm output
__device__ float g_uz[NTOK * 2 * DINNER]; // pre-GLU activations
__device__ float g_h [NTOK * DINNER];     // GLU output
__device__ float g_wh[DMODEL * NHEADS];   // packed head weights
__device__ float g_bh[NHEADS];            // packed head bias

// ---------------- GEMM: 128x128 block, 8x8 microtile, BK=8 ------------------
// C[M,N] = A[M,K] @ B[K,N] (+ epilogue).  M = gridDim.y*128 (rows), row-major.
// MODE 0: C = acc + bias
// MODE 1: C = acc + bias + pos_emb[(row%SEQ)*N + col]          (in_proj, N==DMODEL)
// MODE 2: C = (aux[row*N+col] + acc + bias) * decay(row%SEQ)   (residual, in-place ok)
// MODE 3: heads: mask[row] ? acc+bias : 0; col<128 -> C (frame, stride 128),
//                                          else   -> out2 (sym, stride 256)
template<int MODE>
__global__ __launch_bounds__(256, 2)
void gemm128(const float* __restrict__ A, const float* __restrict__ B,
             const float* __restrict__ bias, float* __restrict__ C,
             int K, int N,
             const float* __restrict__ aux, const float* __restrict__ mask,
             float* __restrict__ out2)
{
    __shared__ float As[8][128];
    __shared__ float Bs[8][128];

    const int tid = threadIdx.x;
    const int tx  = tid & 15;        // 0..15 -> col group
    const int ty  = tid >> 4;        // 0..15 -> row group
    const int r0  = blockIdx.y * 128;
    const int c0  = blockIdx.x * 128;

    const int aRow = tid >> 1;               // 0..127
    const int aCol = (tid & 1) * 4;          // 0 or 4
    const int bRow = tid >> 5;               // 0..7
    const int bCol = (tid & 31) * 4;         // 0..124

    const float* Aptr = A + (size_t)(r0 + aRow) * K + aCol;
    const float* Bptr = B + (size_t)bRow * N + c0 + bCol;

    float acc[8][8];
    #pragma unroll
    for (int i = 0; i < 8; i++)
        #pragma unroll
        for (int j = 0; j < 8; j++) acc[i][j] = 0.f;

    // prologue: fetch first tile into registers
    float4 a4 = *(const float4*)(Aptr);
    float4 b4 = *(const float4*)(Bptr);

    for (int kt = 0; kt < K; kt += 8) {
        As[aCol + 0][aRow] = a4.x;
        As[aCol + 1][aRow] = a4.y;
        As[aCol + 2][aRow] = a4.z;
        As[aCol + 3][aRow] = a4.w;
        *(float4*)(&Bs[bRow][bCol]) = b4;
        __syncthreads();

        if (kt + 8 < K) {   // prefetch next tile while computing
            a4 = *(const float4*)(Aptr + kt + 8);
            b4 = *(const float4*)(Bptr + (size_t)(kt + 8) * N);
        }

        #pragma unroll
        for (int k = 0; k < 8; k++) {
            float af[8], bf[8];
            *(float4*)(af)     = *(const float4*)(&As[k][ty * 8]);
            *(float4*)(af + 4) = *(const float4*)(&As[k][ty * 8 + 4]);
            *(float4*)(bf)     = *(const float4*)(&Bs[k][tx * 8]);
            *(float4*)(bf + 4) = *(const float4*)(&Bs[k][tx * 8 + 4]);
            #pragma unroll
            for (int i = 0; i < 8; i++)
                #pragma unroll
                for (int j = 0; j < 8; j++)
                    acc[i][j] = fmaf(af[i], bf[j], acc[i][j]);
        }
        __syncthreads();
    }

    // ------------------------------ epilogue --------------------------------
    #pragma unroll
    for (int i = 0; i < 8; i++) {
        const int row = r0 + ty * 8 + i;
        const int s   = row & (SEQ - 1);
        float dec = 1.0f;
        if (MODE == 2) dec = (((s + 1) % 10) == 0) ? 0.1f : 1.0f;
        float mk = 1.0f;
        if (MODE == 3) {
            // works whether mask was materialized as int32 or float32
            mk = (((const int*)mask)[row] != 0) ? 1.0f : 0.0f;
        }
        #pragma unroll
        for (int jj = 0; jj < 2; jj++) {
            const int col = c0 + tx * 8 + jj * 4;
            float4 bv = *(const float4*)(bias + col);
            float4 r;
            r.x = acc[i][jj*4+0] + bv.x;
            r.y = acc[i][jj*4+1] + bv.y;
            r.z = acc[i][jj*4+2] + bv.z;
            r.w = acc[i][jj*4+3] + bv.w;
            if (MODE == 1) {
                float4 p = *(const float4*)(aux + (size_t)s * N + col);
                r.x += p.x; r.y += p.y; r.z += p.z; r.w += p.w;
            }
            if (MODE == 2) {
                float4 xv = *(const float4*)(aux + (size_t)row * N + col);
                r.x = (r.x + xv.x) * dec;
                r.y = (r.y + xv.y) * dec;
                r.z = (r.z + xv.z) * dec;
                r.w = (r.w + xv.w) * dec;
            }
            if (MODE == 3) {
                r.x *= mk; r.y *= mk; r.z *= mk; r.w *= mk;
                if (col < FDIM)
                    *(float4*)(C + (size_t)row * FDIM + col) = r;
                else
                    *(float4*)(out2 + (size_t)row * VOCAB + (col - FDIM)) = r;
            } else {
                *(float4*)(C + (size_t)row * N + col) = r;
            }
        }
    }
}

// ---------------- LayerNorm: one warp per row (D=512) -----------------------
__global__ __launch_bounds__(256)
void ln_kernel(const float* __restrict__ x, const float* __restrict__ sc,
               const float* __restrict__ bi, float* __restrict__ out)
{
    const int row  = blockIdx.x * 8 + threadIdx.y;
    const int lane = threadIdx.x;
    const float4* xr = (const float4*)(x + (size_t)row * DMODEL);

    float4 v[4];
    float s = 0.f;
    #pragma unroll
    for (int i = 0; i < 4; i++) {
        v[i] = xr[lane + 32 * i];
        s += v[i].x + v[i].y + v[i].z + v[i].w;
    }
    #pragma unroll
    for (int o = 16; o > 0; o >>= 1) s += __shfl_xor_sync(0xffffffffu, s, o);
    const float mu = s * (1.0f / DMODEL);

    float q = 0.f;
    #pragma unroll
    for (int i = 0; i < 4; i++) {
        float dx = v[i].x - mu; q += dx * dx;
        dx = v[i].y - mu; q += dx * dx;
        dx = v[i].z - mu; q += dx * dx;
        dx = v[i].w - mu; q += dx * dx;
    }
    #pragma unroll
    for (int o = 16; o > 0; o >>= 1) q += __shfl_xor_sync(0xffffffffu, q, o);
    const float inv = rsqrtf(q * (1.0f / DMODEL) + 1e-5f);

    const float4* s4 = (const float4*)sc;
    const float4* b4 = (const float4*)bi;
    float4* o4 = (float4*)(out + (size_t)row * DMODEL);
    #pragma unroll
    for (int i = 0; i < 4; i++) {
        const int c = lane + 32 * i;
        float4 sv = s4[c], bv = b4[c], r;
        r.x = (v[i].x - mu) * inv * sv.x + bv.x;
        r.y = (v[i].y - mu) * inv * sv.y + bv.y;
        r.z = (v[i].z - mu) * inv * sv.z + bv.z;
        r.w = (v[i].w - mu) * inv * sv.w + bv.w;
        o4[c] = r;
    }
}

// ---------------- GLU: h = u * silu(g) ---------------------------------------
__global__ __launch_bounds__(256)
void glu_kernel(const float* __restrict__ uz, float* __restrict__ h)
{
    const int row = blockIdx.x;
    const int c4  = threadIdx.x;   // 0..255, 4 floats each -> 1024 cols
    float4 u = *(const float4*)(uz + (size_t)row * (2 * DINNER) + c4 * 4);
    float4 g = *(const float4*)(uz + (size_t)row * (2 * DINNER) + DINNER + c4 * 4);
    float4 r;
    r.x = u.x * g.x / (1.0f + expf(-g.x));
    r.y = u.y * g.y / (1.0f + expf(-g.y));
    r.z = u.z * g.z / (1.0f + expf(-g.z));
    r.w = u.w * g.w / (1.0f + expf(-g.w));
    *(float4*)(h + (size_t)row * DINNER + c4 * 4) = r;
}

// ---------------- pack head weights into one [512,384] matrix ---------------
__global__ void pack_heads(const float* __restrict__ Wf, const float* __restrict__ bf,
                           const float* __restrict__ Ws, const float* __restrict__ bs,
                           float* __restrict__ wh, float* __restrict__ bh)
{
    const int i = blockIdx.x * blockDim.x + threadIdx.x;
    if (i < DMODEL * NHEADS) {
        const int r = i / NHEADS, c = i % NHEADS;
        wh[i] = (c < FDIM) ? Wf[r * FDIM + c] : Ws[r * VOCAB + (c - FDIM)];
    }
    if (i < NHEADS) bh[i] = (i < FDIM) ? bf[i] : bs[i - FDIM];
}

// -----------------------------------------------------------------------------
extern "C" void kernel_launch(void* const* d_in, const int* in_sizes, int n_in,
                              void* d_out, int out_size)
{
    const float* frames    = (const float*)d_in[0];
    const float* mask      = (const float*)d_in[1];   // bool -> int32/float32; tested via !=0 bits
    const float* W_in_proj = (const float*)d_in[2];
    const float* b_in_proj = (const float*)d_in[3];
    const float* pos_emb   = (const float*)d_in[4];
    const float* ln_scale  = (const float*)d_in[5];
    const float* ln_bias   = (const float*)d_in[6];
    const float* W_in      = (const float*)d_in[7];
    const float* b_in      = (const float*)d_in[8];
    const float* W_out     = (const float*)d_in[9];
    const float* b_out     = (const float*)d_in[10];
    const float* fn_scale  = (const float*)d_in[11];
    const float* fn_bias   = (const float*)d_in[12];
    const float* W_frame   = (const float*)d_in[13];
    const float* b_frame   = (const float*)d_in[14];
    const float* W_sym     = (const float*)d_in[15];
    const float* b_sym     = (const float*)d_in[16];

    float *px, *pn, *puz, *ph, *pwh, *pbh;
    cudaGetSymbolAddress((void**)&px,  g_x);
    cudaGetSymbolAddress((void**)&pn,  g_n);
    cudaGetSymbolAddress((void**)&puz, g_uz);
    cudaGetSymbolAddress((void**)&ph,  g_h);
    cudaGetSymbolAddress((void**)&pwh, g_wh);
    cudaGetSymbolAddress((void**)&pbh, g_bh);

    float* out_frame = (float*)d_out;                         // [NTOK,128]
    float* out_sym   = (float*)d_out + (size_t)NTOK * FDIM;   // [NTOK,256]

    const dim3 lnb(32, 8);
    const int  lng = NTOK / 8;

    // 1) in_proj + pos_emb:  x = frames @ W_in_proj + b + pos_emb
    {
        dim3 grid(DMODEL / 128, NTOK / 128);   // (4,128)
        gemm128<1><<<grid, 256>>>(frames, W_in_proj, b_in_proj, px,
                                  FDIM, DMODEL, pos_emb, nullptr, nullptr);
    }

    // 2) layers
    for (int l = 0; l < NLAYERS; l++) {
        ln_kernel<<<lng, lnb>>>(px, ln_scale + l * DMODEL, ln_bias + l * DMODEL, pn);

        dim3 g1(2 * DINNER / 128, NTOK / 128); // (16,128)
        gemm128<0><<<g1, 256>>>(pn, W_in + (size_t)l * DMODEL * 2 * DINNER,
                                b_in + (size_t)l * 2 * DINNER, puz,
                                DMODEL, 2 * DINNER, nullptr, nullptr, nullptr);

        glu_kernel<<<NTOK, 256>>>(puz, ph);

        dim3 g2(DMODEL / 128, NTOK / 128);     // (4,128)
        gemm128<2><<<g2, 256>>>(ph, W_out + (size_t)l * DINNER * DMODEL,
                                b_out + (size_t)l * DMODEL, px,
                                DINNER, DMODEL, px, nullptr, nullptr);
    }

    // 3) final LN
    ln_kernel<<<lng, lnb>>>(px, fn_scale, fn_bias, pn);

    // 4) heads (packed into one N=384 GEMM with mask epilogue)
    pack_heads<<<(DMODEL * NHEADS + 255) / 256, 256>>>(W_frame, b_frame, W_sym, b_sym, pwh, pbh);
    {
        dim3 grid(NHEADS / 128, NTOK / 128);   // (3,128)
        gemm128<3><<<grid, 256>>>(pn, pwh, pbh, out_frame,
                                  DMODEL, NHEADS, nullptr, mask, out_sym);
    }
}

// round 3
// speedup vs baseline: 1.3415x; 1.3415x over previous
#include <cuda_runtime.h>
#include <cuda_bf16.h>
#include <math.h>
#include <stdint.h>

#define BATCH   8
#define SEQ     2048
#define NTOK    16384
#define FDIM    128
#define DMODEL  512
#define DINNER  1024
#define NLAYERS 4
#define VOCAB   256
#define NHEADS  384

// ---------------- scratch (device globals; no allocs) ----------------
__device__ float g_x [NTOK * DMODEL];
__device__ float g_n [NTOK * DMODEL];
__device__ float g_uz[NTOK * 2 * DINNER];
__device__ float g_h [NTOK * DINNER];
__device__ float g_bt_inproj[DMODEL * FDIM];                 // [N,K] = [512,128]
__device__ float g_bt_win   [NLAYERS * 2 * DINNER * DMODEL]; // [2048,512] x4
__device__ float g_bt_wout  [NLAYERS * DMODEL * DINNER];     // [512,1024] x4
__device__ float g_wh_t     [NHEADS * DMODEL];               // [384,512]
__device__ float g_bh       [NHEADS];

// ---------------- helpers ----------------
__device__ __forceinline__ uint32_t f2t(float x) {   // fp32 -> tf32 (RNA rounding)
    uint32_t r; asm("cvt.rna.tf32.f32 %0, %1;" : "=r"(r) : "f"(x)); return r;
}
__device__ __forceinline__ void mma8(float* d, const uint32_t* a, const uint32_t* b) {
    asm volatile("mma.sync.aligned.m16n8k8.row.col.f32.tf32.tf32.f32 "
                 "{%0,%1,%2,%3}, {%4,%5,%6,%7}, {%8,%9}, {%0,%1,%2,%3};"
                 : "+f"(d[0]), "+f"(d[1]), "+f"(d[2]), "+f"(d[3])
                 : "r"(a[0]), "r"(a[1]), "r"(a[2]), "r"(a[3]), "r"(b[0]), "r"(b[1]));
}

#define SSTRIDE 132   // padded word stride for [k][m] tiles: bank = (4c+r)%32, conflict-free

// ---------------- tf32 mma.sync GEMM ----------------
// C[128 x 128 per CTA] = A[M,K] @ Bt[N,K]^T, K % 32 == 0.
// MODE 0: C = acc + bias                     (row stride Nfull)
// MODE 1: C = acc + bias + pos_emb[s,col]
// MODE 2: C = (aux + acc + bias) * decay(s)  (in-place residual)
// MODE 3: heads: mask ? acc+bias : 0 ; col<128 -> C(frame,128) else out2(sym,256)
template<int MODE>
__global__ __launch_bounds__(256, 2)
void gemm_mma(const float* __restrict__ A, const float* __restrict__ Bt,
              const float* __restrict__ bias, float* __restrict__ C,
              int K, int Nfull,
              const float* __restrict__ aux, const int* __restrict__ mask,
              float* __restrict__ out2)
{
    __shared__ uint32_t As[32 * SSTRIDE];   // [k][m], tf32 bits
    __shared__ uint32_t Bs[32 * SSTRIDE];   // [k][n], tf32 bits

    const int tid  = threadIdx.x;
    const int wid  = tid >> 5, lane = tid & 31;
    const int r    = lane >> 2, c = lane & 3;
    const int wm   = (wid & 1) * 64;        // warp M offset within CTA tile
    const int wn   = (wid >> 1) * 32;       // warp N offset
    const int r0   = blockIdx.y * 128;
    const int c0   = blockIdx.x * 128;

    float acc[4][4][4];
    #pragma unroll
    for (int mt = 0; mt < 4; mt++)
        #pragma unroll
        for (int nt = 0; nt < 4; nt++)
            #pragma unroll
            for (int q = 0; q < 4; q++) acc[mt][nt][q] = 0.f;

    const int ldRow = tid & 127;            // global row/col this thread loads
    const int ldKg  = tid >> 7;             // k-group base (0/1), advance by 2

    for (int kc = 0; kc < K; kc += 32) {
        // --- stage A: 128 rows x 32 k  (float4 loads, tf32 convert, [k][m] store)
        #pragma unroll
        for (int i = 0; i < 4; i++) {
            const int kg = ldKg + 2 * i;    // 0..7
            const float4 v = *(const float4*)(A + (size_t)(r0 + ldRow) * K + kc + kg * 4);
            uint32_t* p = &As[(kg * 4) * SSTRIDE + ldRow];
            p[0]           = f2t(v.x);
            p[SSTRIDE]     = f2t(v.y);
            p[2 * SSTRIDE] = f2t(v.z);
            p[3 * SSTRIDE] = f2t(v.w);
        }
        // --- stage B: 128 n-rows x 32 k
        #pragma unroll
        for (int i = 0; i < 4; i++) {
            const int kg = ldKg + 2 * i;
            const float4 v = *(const float4*)(Bt + (size_t)(c0 + ldRow) * K + kc + kg * 4);
            uint32_t* p = &Bs[(kg * 4) * SSTRIDE + ldRow];
            p[0]           = f2t(v.x);
            p[SSTRIDE]     = f2t(v.y);
            p[2 * SSTRIDE] = f2t(v.z);
            p[3 * SSTRIDE] = f2t(v.w);
        }
        __syncthreads();

        #pragma unroll
        for (int ks = 0; ks < 4; ks++) {
            const int kb = ks * 8;
            uint32_t af[4][4], bf[4][2];
            #pragma unroll
            for (int mt = 0; mt < 4; mt++) {
                const uint32_t* p = &As[(kb + c) * SSTRIDE + wm + mt * 16 + r];
                af[mt][0] = p[0];
                af[mt][1] = p[8];
                af[mt][2] = p[4 * SSTRIDE];
                af[mt][3] = p[4 * SSTRIDE + 8];
            }
            #pragma unroll
            for (int nt = 0; nt < 4; nt++) {
                const uint32_t* p = &Bs[(kb + c) * SSTRIDE + wn + nt * 8 + r];
                bf[nt][0] = p[0];
                bf[nt][1] = p[4 * SSTRIDE];
            }
            #pragma unroll
            for (int mt = 0; mt < 4; mt++)
                #pragma unroll
                for (int nt = 0; nt < 4; nt++)
                    mma8(acc[mt][nt], af[mt], bf[nt]);
        }
        __syncthreads();
    }

    // ---------------- epilogue (C fragment: rows r, r+8; cols 2c, 2c+1) ----------------
    #pragma unroll
    for (int mt = 0; mt < 4; mt++) {
        #pragma unroll
        for (int h = 0; h < 2; h++) {       // h=0 -> regs 0,1 ; h=1 -> regs 2,3
            const int row = r0 + wm + mt * 16 + r + h * 8;
            const int s   = row & (SEQ - 1);
            float dec = 1.0f, mk = 1.0f;
            if (MODE == 2) dec = (((s + 1) % 10) == 0) ? 0.1f : 1.0f;
            if (MODE == 3) mk  = (mask[row] != 0) ? 1.0f : 0.0f;
            #pragma unroll
            for (int nt = 0; nt < 4; nt++) {
                const int col = c0 + wn + nt * 8 + 2 * c;
                float2 bv = *(const float2*)(bias + col);
                float2 v;
                v.x = acc[mt][nt][2 * h + 0] + bv.x;
                v.y = acc[mt][nt][2 * h + 1] + bv.y;
                if (MODE == 1) {
                    float2 p = *(const float2*)(aux + (size_t)s * DMODEL + col);
                    v.x += p.x; v.y += p.y;
                }
                if (MODE == 2) {
                    float2 xv = *(const float2*)(aux + (size_t)row * Nfull + col);
                    v.x = (v.x + xv.x) * dec;
                    v.y = (v.y + xv.y) * dec;
                }
                if (MODE == 3) {
                    v.x *= mk; v.y *= mk;
                    if (col < FDIM)
                        *(float2*)(C + (size_t)row * FDIM + col) = v;
                    else
                        *(float2*)(out2 + (size_t)row * VOCAB + (col - FDIM)) = v;
                } else {
                    *(float2*)(C + (size_t)row * Nfull + col) = v;
                }
            }
        }
    }
}

// ---------------- weight transpose: out[N,K] = in[K,N]^T ----------------
__global__ void transpose_k(const float* __restrict__ in, float* __restrict__ out, int K, int N)
{
    __shared__ float t[32][33];
    const int n0 = blockIdx.x * 32, k0 = blockIdx.y * 32;
    const int x = threadIdx.x, y = threadIdx.y;
    #pragma unroll
    for (int i = 0; i < 32; i += 8)
        t[y + i][x] = in[(size_t)(k0 + y + i) * N + n0 + x];
    __syncthreads();
    #pragma unroll
    for (int i = 0; i < 32; i += 8)
        out[(size_t)(n0 + y + i) * K + k0 + x] = t[x][y + i];
}

// ---------------- pack head weights transposed: wht[384,512] ----------------
__global__ void pack_heads_t(const float* __restrict__ Wf, const float* __restrict__ bf,
                             const float* __restrict__ Ws, const float* __restrict__ bs,
                             float* __restrict__ wht, float* __restrict__ bh)
{
    const int i = blockIdx.x * 256 + threadIdx.x;
    if (i < DMODEL * NHEADS) {
        const int r = i / NHEADS, c = i % NHEADS;
        wht[(size_t)c * DMODEL + r] = (c < FDIM) ? Wf[r * FDIM + c] : Ws[r * VOCAB + (c - FDIM)];
    }
    if (i < NHEADS) bh[i] = (i < FDIM) ? bf[i] : bs[i - FDIM];
}

// ---------------- LayerNorm: one warp per row (D=512) ----------------
__global__ __launch_bounds__(256)
void ln_kernel(const float* __restrict__ x, const float* __restrict__ sc,
               const float* __restrict__ bi, float* __restrict__ out)
{
    const int row  = blockIdx.x * 8 + threadIdx.y;
    const int lane = threadIdx.x;
    const float4* xr = (const float4*)(x + (size_t)row * DMODEL);
    float4 v[4]; float s = 0.f;
    #pragma unroll
    for (int i = 0; i < 4; i++) { v[i] = xr[lane + 32*i]; s += v[i].x + v[i].y + v[i].z + v[i].w; }
    #pragma unroll
    for (int o = 16; o > 0; o >>= 1) s += __shfl_xor_sync(0xffffffffu, s, o);
    const float mu = s * (1.0f / DMODEL);
    float q = 0.f;
    #pragma unroll
    for (int i = 0; i < 4; i++) {
        float d;
        d = v[i].x - mu; q += d*d;  d = v[i].y - mu; q += d*d;
        d = v[i].z - mu; q += d*d;  d = v[i].w - mu; q += d*d;
    }
    #pragma unroll
    for (int o = 16; o > 0; o >>= 1) q += __shfl_xor_sync(0xffffffffu, q, o);
    const float inv = rsqrtf(q * (1.0f / DMODEL) + 1e-5f);
    const float4* s4 = (const float4*)sc;
    const float4* b4 = (const float4*)bi;
    float4* o4 = (float4*)(out + (size_t)row * DMODEL);
    #pragma unroll
    for (int i = 0; i < 4; i++) {
        const int cc = lane + 32*i;
        float4 sv = s4[cc], bv = b4[cc], rr;
        rr.x = (v[i].x - mu) * inv * sv.x + bv.x;
        rr.y = (v[i].y - mu) * inv * sv.y + bv.y;
        rr.z = (v[i].z - mu) * inv * sv.z + bv.z;
        rr.w = (v[i].w - mu) * inv * sv.w + bv.w;
        o4[cc] = rr;
    }
}

// ---------------- GLU: h = u * silu(g) ----------------
__global__ __launch_bounds__(256)
void glu_kernel(const float* __restrict__ uz, float* __restrict__ h)
{
    const int row = blockIdx.x;
    const int c4  = threadIdx.x;
    float4 u = *(const float4*)(uz + (size_t)row * (2*DINNER) + c4*4);
    float4 g = *(const float4*)(uz + (size_t)row * (2*DINNER) + DINNER + c4*4);
    float4 r;
    r.x = u.x * g.x / (1.0f + expf(-g.x));
    r.y = u.y * g.y / (1.0f + expf(-g.y));
    r.z = u.z * g.z / (1.0f + expf(-g.z));
    r.w = u.w * g.w / (1.0f + expf(-g.w));
    *(float4*)(h + (size_t)row * DINNER + c4*4) = r;
}

// -----------------------------------------------------------------------------
extern "C" void kernel_launch(void* const* d_in, const int* in_sizes, int n_in,
                              void* d_out, int out_size)
{
    const float* frames    = (const float*)d_in[0];
    const int*   mask      = (const int*)d_in[1];
    const float* W_in_proj = (const float*)d_in[2];
    const float* b_in_proj = (const float*)d_in[3];
    const float* pos_emb   = (const float*)d_in[4];
    const float* ln_scale  = (const float*)d_in[5];
    const float* ln_bias   = (const float*)d_in[6];
    const float* W_in      = (const float*)d_in[7];
    const float* b_in      = (const float*)d_in[8];
    const float* W_out     = (const float*)d_in[9];
    const float* b_out     = (const float*)d_in[10];
    const float* fn_scale  = (const float*)d_in[11];
    const float* fn_bias   = (const float*)d_in[12];
    const float* W_frame   = (const float*)d_in[13];
    const float* b_frame   = (const float*)d_in[14];
    const float* W_sym     = (const float*)d_in[15];
    const float* b_sym     = (const float*)d_in[16];

    float *px, *pn, *puz, *ph, *pbtP, *pbtI, *pbtO, *pwht, *pbh;
    cudaGetSymbolAddress((void**)&px,   g_x);
    cudaGetSymbolAddress((void**)&pn,   g_n);
    cudaGetSymbolAddress((void**)&puz,  g_uz);
    cudaGetSymbolAddress((void**)&ph,   g_h);
    cudaGetSymbolAddress((void**)&pbtP, g_bt_inproj);
    cudaGetSymbolAddress((void**)&pbtI, g_bt_win);
    cudaGetSymbolAddress((void**)&pbtO, g_bt_wout);
    cudaGetSymbolAddress((void**)&pwht, g_wh_t);
    cudaGetSymbolAddress((void**)&pbh,  g_bh);

    float* out_frame = (float*)d_out;
    float* out_sym   = (float*)d_out + (size_t)NTOK * FDIM;

    // ---- weight prep (every call; small) ----
    {
        dim3 b(32, 8);
        transpose_k<<<dim3(DMODEL/32, FDIM/32), b>>>(W_in_proj, pbtP, FDIM, DMODEL);
        for (int l = 0; l < NLAYERS; l++) {
            transpose_k<<<dim3(2*DINNER/32, DMODEL/32), b>>>(
                W_in + (size_t)l * DMODEL * 2 * DINNER,
                pbtI + (size_t)l * 2 * DINNER * DMODEL, DMODEL, 2*DINNER);
            transpose_k<<<dim3(DMODEL/32, DINNER/32), b>>>(
                W_out + (size_t)l * DINNER * DMODEL,
                pbtO + (size_t)l * DMODEL * DINNER, DINNER, DMODEL);
        }
        pack_heads_t<<<(DMODEL*NHEADS + 255)/256, 256>>>(W_frame, b_frame, W_sym, b_sym, pwht, pbh);
    }

    const dim3 lnb(32, 8);
    const int  lng = NTOK / 8;

    // 1) in_proj + pos_emb
    gemm_mma<1><<<dim3(DMODEL/128, NTOK/128), 256>>>(
        frames, pbtP, b_in_proj, px, FDIM, DMODEL, pos_emb, nullptr, nullptr);

    // 2) layers
    for (int l = 0; l < NLAYERS; l++) {
        ln_kernel<<<lng, lnb>>>(px, ln_scale + l*DMODEL, ln_bias + l*DMODEL, pn);

        gemm_mma<0><<<dim3(2*DINNER/128, NTOK/128), 256>>>(
            pn, pbtI + (size_t)l * 2*DINNER*DMODEL,
            b_in + (size_t)l * 2*DINNER, puz, DMODEL, 2*DINNER,
            nullptr, nullptr, nullptr);

        glu_kernel<<<NTOK, 256>>>(puz, ph);

        gemm_mma<2><<<dim3(DMODEL/128, NTOK/128), 256>>>(
            ph, pbtO + (size_t)l * DMODEL*DINNER,
            b_out + (size_t)l * DMODEL, px, DINNER, DMODEL,
            px, nullptr, nullptr);
    }

    // 3) final LN
    ln_kernel<<<lng, lnb>>>(px, fn_scale, fn_bias, pn);

    // 4) heads (N=384, padded CTA grid of 3 x-tiles)
    gemm_mma<3><<<dim3(NHEADS/128, NTOK/128), 256>>>(
        pn, pwht, pbh, out_frame, DMODEL, NHEADS,
        nullptr, mask, out_sym);
}

// round 4
// speedup vs baseline: 2.9484x; 2.1978x over previous
#include <cuda_runtime.h>
#include <cuda_bf16.h>
#include <math.h>
#include <stdint.h>

#define BATCH   8
#define SEQ     2048
#define NTOK    16384
#define FDIM    128
#define DMODEL  512
#define DINNER  1024
#define NLAYERS 4
#define VOCAB   256
#define NHEADS  384

// ---------------- scratch (device globals; no allocs) ----------------
__device__ float g_x [NTOK * DMODEL];
__device__ float g_n [NTOK * DMODEL];
__device__ float g_h [NTOK * DINNER];
__device__ float g_bt_inproj[DMODEL * FDIM];
__device__ float g_bt_win   [NLAYERS * 2 * DINNER * DMODEL];
__device__ float g_bt_wout  [NLAYERS * DMODEL * DINNER];
__device__ float g_wh_t     [NHEADS * DMODEL];
__device__ float g_bh       [NHEADS];

// ---------------- helpers ----------------
__device__ __forceinline__ uint32_t smem_u32(const void* p) {
    uint32_t a;
    asm("{ .reg .u64 t; cvta.to.shared.u64 t, %1; cvt.u32.u64 %0, t; }" : "=r"(a) : "l"(p));
    return a;
}
__device__ __forceinline__ uint32_t f2t(float x) {   // fp32 -> tf32 (RNA)
    uint32_t r; asm("cvt.rna.tf32.f32 %0, %1;" : "=r"(r) : "f"(x)); return r;
}
__device__ __forceinline__ void mma8(float* d, const uint32_t* a, const uint32_t* b) {
    asm volatile("mma.sync.aligned.m16n8k8.row.col.f32.tf32.tf32.f32 "
                 "{%0,%1,%2,%3}, {%4,%5,%6,%7}, {%8,%9}, {%0,%1,%2,%3};"
                 : "+f"(d[0]), "+f"(d[1]), "+f"(d[2]), "+f"(d[3])
                 : "r"(a[0]), "r"(a[1]), "r"(a[2]), "r"(a[3]), "r"(b[0]), "r"(b[1]));
}
__device__ __forceinline__ void cpa16(uint32_t s, const void* g) {
    asm volatile("cp.async.cg.shared.global [%0], [%1], 16;" :: "r"(s), "l"(g));
}
#define CP_COMMIT() asm volatile("cp.async.commit_group;")
#define CP_WAIT1()  asm volatile("cp.async.wait_group 1;")
#define CP_WAIT0()  asm volatile("cp.async.wait_group 0;")

#define LDK 40                 // row stride in floats: 16B-aligned, conflict-free frags
#define TILE_F (128 * LDK)     // floats per staged matrix (5120)
#define STAGE_F (2 * TILE_F)   // A+B per stage (10240)
#define SMEM_BYTES (2 * STAGE_F * 4)   // 81920

// ---------------- tf32 mma.sync GEMM, cp.async double-buffered ----------------
// MODE 1: C = acc + bias + pos_emb[s,col]          (in_proj, Nfull=DMODEL)
// MODE 2: C = (aux + acc + bias) * decay(s)        (residual, in-place)
// MODE 3: heads: mask ? acc+bias : 0; split frame/sym
// MODE 4: GLU fused: CTA covers 64 u-cols + 64 g-cols; writes h = u*silu(g)
template<int MODE>
__global__ __launch_bounds__(256, 2)
void gemm_mma(const float* __restrict__ A, const float* __restrict__ Bt,
              const float* __restrict__ bias, float* __restrict__ C,
              int K, int Nfull,
              const float* __restrict__ aux, const int* __restrict__ mask,
              float* __restrict__ out2)
{
    extern __shared__ float smem[];
    const int tid  = threadIdx.x;
    const int wid  = tid >> 5, lane = tid & 31;
    const int r    = lane >> 2, c = lane & 3;
    const int wm   = (wid & 1) * 64;
    const int wn   = (wid >> 1) * 32;
    const int r0   = blockIdx.y * 128;
    const int c0   = blockIdx.x * ((MODE == 4) ? 64 : 128);

    // staging coordinates: 8 float4 per 128-row matrix per thread (4 iters)
    const int srw = tid >> 3;            // base row 0..31 (+32 per iter)
    const int sf  = (tid & 7) * 4;       // k offset within chunk (0,4,..28)

    // B global row for staged row t
    auto browf = [&](int t) -> int {
        if (MODE == 4) {
            const int wq = t >> 5, i5 = t & 31;
            return c0 + wq * 16 + (i5 & 15) + ((i5 >> 4) ? DINNER : 0);
        }
        return c0 + t;
    };

    const uint32_t sbase = smem_u32(smem);
    const int nch = K >> 5;

    auto stage = [&](int ch, int buf) {
        const int kc = ch << 5;
        const uint32_t aB = sbase + (buf * STAGE_F) * 4;
        const uint32_t bB = aB + TILE_F * 4;
        #pragma unroll
        for (int i = 0; i < 4; i++) {
            const int rw = srw + 32 * i;
            cpa16(aB + (rw * LDK + sf) * 4, A + (size_t)(r0 + rw) * K + kc + sf);
        }
        #pragma unroll
        for (int i = 0; i < 4; i++) {
            const int rw = srw + 32 * i;
            cpa16(bB + (rw * LDK + sf) * 4, Bt + (size_t)browf(rw) * K + kc + sf);
        }
        CP_COMMIT();
    };

    float acc[4][4][4];
    #pragma unroll
    for (int mt = 0; mt < 4; mt++)
        #pragma unroll
        for (int nt = 0; nt < 4; nt++)
            #pragma unroll
            for (int q = 0; q < 4; q++) acc[mt][nt][q] = 0.f;

    stage(0, 0);
    if (nch > 1) stage(1, 1);

    int buf = 0;
    for (int ch = 0; ch < nch; ch++) {
        if (ch + 1 < nch) { CP_WAIT1(); } else { CP_WAIT0(); }
        __syncthreads();

        const float* As = smem + buf * STAGE_F;
        const float* Bs = As + TILE_F;
        #pragma unroll
        for (int ks = 0; ks < 4; ks++) {
            const int kb = ks * 8;
            uint32_t af[4][4], bf[4][2];
            #pragma unroll
            for (int mt = 0; mt < 4; mt++) {
                const float* p = &As[(wm + mt * 16 + r) * LDK + kb + c];
                af[mt][0] = f2t(p[0]);
                af[mt][1] = f2t(p[8 * LDK]);
                af[mt][2] = f2t(p[4]);
                af[mt][3] = f2t(p[8 * LDK + 4]);
            }
            #pragma unroll
            for (int nt = 0; nt < 4; nt++) {
                const float* p = &Bs[(wn + nt * 8 + r) * LDK + kb + c];
                bf[nt][0] = f2t(p[0]);
                bf[nt][1] = f2t(p[4]);
            }
            #pragma unroll
            for (int mt = 0; mt < 4; mt++)
                #pragma unroll
                for (int nt = 0; nt < 4; nt++)
                    mma8(acc[mt][nt], af[mt], bf[nt]);
        }
        __syncthreads();
        if (ch + 2 < nch) stage(ch + 2, buf);
        buf ^= 1;
    }

    // ---------------- epilogue ----------------
    if (MODE == 4) {
        const int wq = wid >> 1;
        #pragma unroll
        for (int mt = 0; mt < 4; mt++) {
            #pragma unroll
            for (int h = 0; h < 2; h++) {
                const int row = r0 + wm + mt * 16 + r + h * 8;
                #pragma unroll
                for (int nt = 0; nt < 2; nt++) {
                    const int ucol = c0 + wq * 16 + nt * 8 + 2 * c;
                    float2 bu = *(const float2*)(bias + ucol);
                    float2 bg = *(const float2*)(bias + DINNER + ucol);
                    float ux = acc[mt][nt][2*h+0] + bu.x;
                    float uy = acc[mt][nt][2*h+1] + bu.y;
                    float gx = acc[mt][nt+2][2*h+0] + bg.x;
                    float gy = acc[mt][nt+2][2*h+1] + bg.y;
                    float2 v;
                    v.x = ux * gx / (1.0f + __expf(-gx));
                    v.y = uy * gy / (1.0f + __expf(-gy));
                    *(float2*)(C + (size_t)row * DINNER + ucol) = v;
                }
            }
        }
        return;
    }

    #pragma unroll
    for (int mt = 0; mt < 4; mt++) {
        #pragma unroll
        for (int h = 0; h < 2; h++) {
            const int row = r0 + wm + mt * 16 + r + h * 8;
            const int s   = row & (SEQ - 1);
            float dec = 1.0f, mk = 1.0f;
            if (MODE == 2) dec = (((s + 1) % 10) == 0) ? 0.1f : 1.0f;
            if (MODE == 3) mk  = (mask[row] != 0) ? 1.0f : 0.0f;
            #pragma unroll
            for (int nt = 0; nt < 4; nt++) {
                const int col = c0 + wn + nt * 8 + 2 * c;
                float2 bv = *(const float2*)(bias + col);
                float2 v;
                v.x = acc[mt][nt][2*h+0] + bv.x;
                v.y = acc[mt][nt][2*h+1] + bv.y;
                if (MODE == 1) {
                    float2 p = *(const float2*)(aux + (size_t)s * DMODEL + col);
                    v.x += p.x; v.y += p.y;
                }
                if (MODE == 2) {
                    float2 xv = *(const float2*)(aux + (size_t)row * Nfull + col);
                    v.x = (v.x + xv.x) * dec;
                    v.y = (v.y + xv.y) * dec;
                }
                if (MODE == 3) {
                    v.x *= mk; v.y *= mk;
                    if (col < FDIM)
                        *(float2*)(C + (size_t)row * FDIM + col) = v;
                    else
                        *(float2*)(out2 + (size_t)row * VOCAB + (col - FDIM)) = v;
                } else {
                    *(float2*)(C + (size_t)row * Nfull + col) = v;
                }
            }
        }
    }
}

// ---------------- weight transpose: out[N,K] = in[K,N]^T ----------------
__global__ void transpose_k(const float* __restrict__ in, float* __restrict__ out, int K, int N)
{
    __shared__ float t[32][33];
    const int n0 = blockIdx.x * 32, k0 = blockIdx.y * 32;
    const int x = threadIdx.x, y = threadIdx.y;
    #pragma unroll
    for (int i = 0; i < 32; i += 8)
        t[y + i][x] = in[(size_t)(k0 + y + i) * N + n0 + x];
    __syncthreads();
    #pragma unroll
    for (int i = 0; i < 32; i += 8)
        out[(size_t)(n0 + y + i) * K + k0 + x] = t[x][y + i];
}

// ---------------- pack head weights transposed: wht[384,512] ----------------
__global__ void pack_heads_t(const float* __restrict__ Wf, const float* __restrict__ bf,
                             const float* __restrict__ Ws, const float* __restrict__ bs,
                             float* __restrict__ wht, float* __restrict__ bh)
{
    const int i = blockIdx.x * 256 + threadIdx.x;
    if (i < DMODEL * NHEADS) {
        const int r = i / NHEADS, c = i % NHEADS;
        wht[(size_t)c * DMODEL + r] = (c < FDIM) ? Wf[r * FDIM + c] : Ws[r * VOCAB + (c - FDIM)];
    }
    if (i < NHEADS) bh[i] = (i < FDIM) ? bf[i] : bs[i - FDIM];
}

// ---------------- LayerNorm: one warp per row (D=512) ----------------
__global__ __launch_bounds__(256)
void ln_kernel(const float* __restrict__ x, const float* __restrict__ sc,
               const float* __restrict__ bi, float* __restrict__ out)
{
    const int row  = blockIdx.x * 8 + threadIdx.y;
    const int lane = threadIdx.x;
    const float4* xr = (const float4*)(x + (size_t)row * DMODEL);
    float4 v[4]; float s = 0.f;
    #pragma unroll
    for (int i = 0; i < 4; i++) { v[i] = xr[lane + 32*i]; s += v[i].x + v[i].y + v[i].z + v[i].w; }
    #pragma unroll
    for (int o = 16; o > 0; o >>= 1) s += __shfl_xor_sync(0xffffffffu, s, o);
    const float mu = s * (1.0f / DMODEL);
    float q = 0.f;
    #pragma unroll
    for (int i = 0; i < 4; i++) {
        float d;
        d = v[i].x - mu; q += d*d;  d = v[i].y - mu; q += d*d;
        d = v[i].z - mu; q += d*d;  d = v[i].w - mu; q += d*d;
    }
    #pragma unroll
    for (int o = 16; o > 0; o >>= 1) q += __shfl_xor_sync(0xffffffffu, q, o);
    const float inv = rsqrtf(q * (1.0f / DMODEL) + 1e-5f);
    const float4* s4 = (const float4*)sc;
    const float4* b4 = (const float4*)bi;
    float4* o4 = (float4*)(out + (size_t)row * DMODEL);
    #pragma unroll
    for (int i = 0; i < 4; i++) {
        const int cc = lane + 32*i;
        float4 sv = s4[cc], bv = b4[cc], rr;
        rr.x = (v[i].x - mu) * inv * sv.x + bv.x;
        rr.y = (v[i].y - mu) * inv * sv.y + bv.y;
        rr.z = (v[i].z - mu) * inv * sv.z + bv.z;
        rr.w = (v[i].w - mu) * inv * sv.w + bv.w;
        o4[cc] = rr;
    }
}

// -----------------------------------------------------------------------------
extern "C" void kernel_launch(void* const* d_in, const int* in_sizes, int n_in,
                              void* d_out, int out_size)
{
    const float* frames    = (const float*)d_in[0];
    const int*   mask      = (const int*)d_in[1];
    const float* W_in_proj = (const float*)d_in[2];
    const float* b_in_proj = (const float*)d_in[3];
    const float* pos_emb   = (const float*)d_in[4];
    const float* ln_scale  = (const float*)d_in[5];
    const float* ln_bias   = (const float*)d_in[6];
    const float* W_in      = (const float*)d_in[7];
    const float* b_in      = (const float*)d_in[8];
    const float* W_out     = (const float*)d_in[9];
    const float* b_out     = (const float*)d_in[10];
    const float* fn_scale  = (const float*)d_in[11];
    const float* fn_bias   = (const float*)d_in[12];
    const float* W_frame   = (const float*)d_in[13];
    const float* b_frame   = (const float*)d_in[14];
    const float* W_sym     = (const float*)d_in[15];
    const float* b_sym     = (const float*)d_in[16];

    float *px, *pn, *ph, *pbtP, *pbtI, *pbtO, *pwht, *pbh;
    cudaGetSymbolAddress((void**)&px,   g_x);
    cudaGetSymbolAddress((void**)&pn,   g_n);
    cudaGetSymbolAddress((void**)&ph,   g_h);
    cudaGetSymbolAddress((void**)&pbtP, g_bt_inproj);
    cudaGetSymbolAddress((void**)&pbtI, g_bt_win);
    cudaGetSymbolAddress((void**)&pbtO, g_bt_wout);
    cudaGetSymbolAddress((void**)&pwht, g_wh_t);
    cudaGetSymbolAddress((void**)&pbh,  g_bh);

    float* out_frame = (float*)d_out;
    float* out_sym   = (float*)d_out + (size_t)NTOK * FDIM;

    cudaFuncSetAttribute(gemm_mma<1>, cudaFuncAttributeMaxDynamicSharedMemorySize, SMEM_BYTES);
    cudaFuncSetAttribute(gemm_mma<2>, cudaFuncAttributeMaxDynamicSharedMemorySize, SMEM_BYTES);
    cudaFuncSetAttribute(gemm_mma<3>, cudaFuncAttributeMaxDynamicSharedMemorySize, SMEM_BYTES);
    cudaFuncSetAttribute(gemm_mma<4>, cudaFuncAttributeMaxDynamicSharedMemorySize, SMEM_BYTES);

    // ---- weight prep ----
    {
        dim3 b(32, 8);
        transpose_k<<<dim3(DMODEL/32, FDIM/32), b>>>(W_in_proj, pbtP, FDIM, DMODEL);
        for (int l = 0; l < NLAYERS; l++) {
            transpose_k<<<dim3(2*DINNER/32, DMODEL/32), b>>>(
                W_in + (size_t)l * DMODEL * 2 * DINNER,
                pbtI + (size_t)l * 2 * DINNER * DMODEL, DMODEL, 2*DINNER);
            transpose_k<<<dim3(DMODEL/32, DINNER/32), b>>>(
                W_out + (size_t)l * DINNER * DMODEL,
                pbtO + (size_t)l * DMODEL * DINNER, DINNER, DMODEL);
        }
        pack_heads_t<<<(DMODEL*NHEADS + 255)/256, 256>>>(W_frame, b_frame, W_sym, b_sym, pwht, pbh);
    }

    const dim3 lnb(32, 8);
    const int  lng = NTOK / 8;

    // 1) in_proj + pos_emb
    gemm_mma<1><<<dim3(DMODEL/128, NTOK/128), 256, SMEM_BYTES>>>(
        frames, pbtP, b_in_proj, px, FDIM, DMODEL, pos_emb, nullptr, nullptr);

    // 2) layers: LN -> fused GEMM+GLU -> GEMM+residual
    for (int l = 0; l < NLAYERS; l++) {
        ln_kernel<<<lng, lnb>>>(px, ln_scale + l*DMODEL, ln_bias + l*DMODEL, pn);

        gemm_mma<4><<<dim3(DINNER/64, NTOK/128), 256, SMEM_BYTES>>>(
            pn, pbtI + (size_t)l * 2*DINNER*DMODEL,
            b_in + (size_t)l * 2*DINNER, ph, DMODEL, DINNER,
            nullptr, nullptr, nullptr);

        gemm_mma<2><<<dim3(DMODEL/128, NTOK/128), 256, SMEM_BYTES>>>(
            ph, pbtO + (size_t)l * DMODEL*DINNER,
            b_out + (size_t)l * DMODEL, px, DINNER, DMODEL,
            px, nullptr, nullptr);
    }

    // 3) final LN
    ln_kernel<<<lng, lnb>>>(px, fn_scale, fn_bias, pn);

    // 4) heads
    gemm_mma<3><<<dim3(NHEADS/128, NTOK/128), 256, SMEM_BYTES>>>(
        pn, pwht, pbh, out_frame, DMODEL, NHEADS,
        nullptr, mask, out_sym);
}